// round 5
// baseline (speedup 1.0000x reference)
#include <cuda_runtime.h>
#include <cuda_bf16.h>

// BPMLL loss — depth-minimized single launch.
//   128 blocks x 128 threads; each WARP owns one row (16 elems/lane, 8 LDG.128
//   front-batched -> MLP=8). Row reduce = pure warp shuffle (no smem phase).
//   Block combines its 4 row-partials, does one st.cg + atom.acq_rel; the
//   128th arriving block reads the 128 block-partials (1/thread) and writes out.
//
// Math per element (2 MUFU + 4 FMA):
//   exp(-sigmoid(c)) = e^{-1} * exp(sigmoid(-c)) -> h(x)=exp(sigmoid(x)),
//   x = y ? -c : c. sigmoid = EX2+RCP; exp(s), s in (0,1), degree-4 poly.

#define ROWS   512
#define COLS   512
#define NBLK   128
#define TPB    128
#define ROWS_PER_BLK 4

#define D0 1.00002694f
#define D1 0.99871530f
#define D2 0.50996560f
#define D3 0.13998530f
#define D4 0.06956140f
#define E_INV 0.36787944117144233f

__device__ float        g_block[NBLK];
__device__ unsigned int g_count = 0;

__device__ __forceinline__ void elem(float c, int y,
                                     float& pos, float& neg, int& ys) {
    float x = __int_as_float(__float_as_int(c) ^ (y << 31));  // y ? -c : c
    float t = __expf(-x);                                     // MUFU.EX2
    float s;
    asm("rcp.approx.f32 %0, %1;" : "=f"(s) : "f"(1.0f + t));  // MUFU.RCP
    float h = fmaf(s, D4, D3);
    h = fmaf(h, s, D2);
    h = fmaf(h, s, D1);
    h = fmaf(h, s, D0);
    if (y) { pos += h; ys++; } else { neg += h; }
}

__global__ __launch_bounds__(TPB) void bpmll_kernel(const float* __restrict__ c,
                                                    const int*   __restrict__ y,
                                                    float* __restrict__ out) {
    const int tid  = threadIdx.x;
    const int lane = tid & 31;
    const int warp = tid >> 5;
    const int row  = blockIdx.x * ROWS_PER_BLK + warp;

    const float4* cp = reinterpret_cast<const float4*>(c + (size_t)row * COLS);
    const int4*   yp = reinterpret_cast<const int4*>(y + (size_t)row * COLS);

    // Front-batch all 8 vector loads (MLP=8) before any math.
    float4 cv0 = cp[lane];       float4 cv1 = cp[lane + 32];
    float4 cv2 = cp[lane + 64];  float4 cv3 = cp[lane + 96];
    int4   yv0 = yp[lane];       int4   yv1 = yp[lane + 32];
    int4   yv2 = yp[lane + 64];  int4   yv3 = yp[lane + 96];

    float pos = 0.0f, neg = 0.0f;
    int   ys  = 0;
    elem(cv0.x, yv0.x, pos, neg, ys); elem(cv0.y, yv0.y, pos, neg, ys);
    elem(cv0.z, yv0.z, pos, neg, ys); elem(cv0.w, yv0.w, pos, neg, ys);
    elem(cv1.x, yv1.x, pos, neg, ys); elem(cv1.y, yv1.y, pos, neg, ys);
    elem(cv1.z, yv1.z, pos, neg, ys); elem(cv1.w, yv1.w, pos, neg, ys);
    elem(cv2.x, yv2.x, pos, neg, ys); elem(cv2.y, yv2.y, pos, neg, ys);
    elem(cv2.z, yv2.z, pos, neg, ys); elem(cv2.w, yv2.w, pos, neg, ys);
    elem(cv3.x, yv3.x, pos, neg, ys); elem(cv3.y, yv3.y, pos, neg, ys);
    elem(cv3.z, yv3.z, pos, neg, ys); elem(cv3.w, yv3.w, pos, neg, ys);

    // Warp-level row reduction (interleaved chains overlap shfl latency).
    #pragma unroll
    for (int o = 16; o > 0; o >>= 1) {
        pos += __shfl_down_sync(0xFFFFFFFFu, pos, o);
        neg += __shfl_down_sync(0xFFFFFFFFu, neg, o);
        ys  += __shfl_down_sync(0xFFFFFFFFu, ys,  o);
    }

    __shared__ float sp[ROWS_PER_BLK];
    if (lane == 0) {
        const float yn  = (float)ys;
        const float ybn = (float)(COLS - ys);
        sp[warp] = (E_INV * pos) * neg / (yn * ybn);
    }
    __syncthreads();

    __shared__ bool is_last;
    if (tid == 0) {
        float part = (sp[0] + sp[1]) + (sp[2] + sp[3]);
        asm volatile("st.global.cg.f32 [%0], %1;"
                     :: "l"(&g_block[blockIdx.x]), "f"(part) : "memory");
        unsigned int old;
        asm volatile("atom.acq_rel.gpu.global.add.u32 %0, [%1], %2;"
                     : "=r"(old) : "l"(&g_count), "r"(1u) : "memory");
        is_last = (old == (unsigned)(NBLK - 1));
    }
    __syncthreads();

    if (is_last) {
        float v;
        asm volatile("ld.global.cg.f32 %0, [%1];" : "=f"(v) : "l"(&g_block[tid]));
        #pragma unroll
        for (int o = 16; o > 0; o >>= 1)
            v += __shfl_down_sync(0xFFFFFFFFu, v, o);
        if (lane == 0) sp[warp] = v;
        __syncthreads();
        if (tid == 0) {
            out[0] = ((sp[0] + sp[1]) + (sp[2] + sp[3])) / (float)ROWS;
            asm volatile("st.global.cg.u32 [%0], %1;"
                         :: "l"(&g_count), "r"(0u) : "memory");
        }
    }
}

extern "C" void kernel_launch(void* const* d_in, const int* in_sizes, int n_in,
                              void* d_out, int out_size) {
    const float* c = (const float*)d_in[0];
    const int*   y = (const int*)d_in[1];
    float*       out = (float*)d_out;
    bpmll_kernel<<<NBLK, TPB>>>(c, y, out);
}